// round 17
// baseline (speedup 1.0000x reference)
#include <cuda_runtime.h>
#include <cuda_bf16.h>
#include <mma.h>

using namespace nvcuda;

#define B_    64
#define D_    512
#define N_    1200
#define K_    64
#define NT_   10
#define NTILE 128
#define NPAD  1280
#define EPSF  1e-12f

typedef unsigned int u32;

__device__ __align__(16) float g_a[(size_t)B_ * K_ * NPAD];  // a' fp32, 0-padded
__device__ float g_asum_part[B_ * NT_ * K_];

// ---------------------------------------------------------------------------
// KA: per (b, 128-pixel tile): logits[128n x 64k] = x_raw · W^T via wmma TF32
//     (fp32 accum), 8 chunks of 64 d, cp.async double-buffered (x stays fp32
//     end-to-end: no conversion, no load registers -> max MLP). Sumsq from
//     staged smem; invnorm folded post-GEMM; softmax; writes a' fp32 + asum.
//     Dynamic smem: xs 2x(64x132)f + ws 2x(64x68)f = 100 KB -> 2 CTAs/SM.
// ---------------------------------------------------------------------------
__global__ __launch_bounds__(256) void ka_logits(const float* __restrict__ x,
                                                 const float* __restrict__ w)
{
    extern __shared__ __align__(16) char DSM[];
    float* xs      = reinterpret_cast<float*>(DSM);            // [2][64*132]
    float* ws      = reinterpret_cast<float*>(DSM + 67584);    // [2][64*68]
    float* logit_s = reinterpret_cast<float*>(DSM);            // alias xs: [64][136]
    float* s_red   = reinterpret_cast<float*>(DSM + 67584);    // alias ws: [2][128]
    float* s_wsum  = reinterpret_cast<float*>(DSM + 67584 + 1024); // [4][64]

    const int tid = threadIdx.x, wid = tid >> 5, lid = tid & 31;
    const int tile = blockIdx.x, b = blockIdx.y;
    const int n0 = tile * NTILE;
    const float* xb = x + (size_t)b * D_ * N_;

    const u32 xs_sh = (u32)__cvta_generic_to_shared(xs);
    const u32 ws_sh = (u32)__cvta_generic_to_shared(ws);

#define KA_STAGE(p, ci) do{ const int c_ = (ci)*64; \
    _Pragma("unroll") \
    for (int i_ = 0; i_ < 8; ++i_){ \
        int u_ = tid + 256*i_; int r_ = u_ >> 5, c16 = u_ & 31; \
        int gn_ = n0 + 4*c16; bool v_ = gn_ < N_; \
        const float* s_ = v_ ? (xb + (size_t)(c_ + r_)*N_ + gn_) : xb; \
        u32 d_ = xs_sh + (u32)(p)*33792u + (u32)(r_*132 + 4*c16)*4u; \
        asm volatile("cp.async.cg.shared.global [%0], [%1], 16, %2;" \
                     :: "r"(d_), "l"(s_), "r"(v_ ? 16 : 0)); } \
    _Pragma("unroll") \
    for (int i_ = 0; i_ < 4; ++i_){ \
        int u_ = tid + 256*i_; int k_ = u_ >> 4, c4 = u_ & 15; \
        const float* s_ = w + (size_t)k_*D_ + c_ + 4*c4; \
        u32 d_ = ws_sh + (u32)(p)*17408u + (u32)(k_*68 + 4*c4)*4u; \
        asm volatile("cp.async.ca.shared.global [%0], [%1], 16;" :: "r"(d_), "l"(s_)); } \
    asm volatile("cp.async.commit_group;"); }while(0)

    wmma::fragment<wmma::accumulator, 16, 16, 8, float> cfr[4];
    #pragma unroll
    for (int j = 0; j < 4; ++j) wmma::fill_fragment(cfr[j], 0.f);

    const int sn = tid & 127, sh2 = tid >> 7;   // sumsq mapping
    float sq = 0.f;

    KA_STAGE(0, 0);
    for (int ci = 0; ci < 8; ++ci){
        const int p = ci & 1;
        if (ci < 7){
            KA_STAGE(p ^ 1, ci + 1);
            asm volatile("cp.async.wait_group 1;");
        } else {
            asm volatile("cp.async.wait_group 0;");
        }
        __syncthreads();

        const float* xp = xs + p * 8448;
        #pragma unroll
        for (int r = 0; r < 32; ++r){
            float v = xp[(sh2*32 + r)*132 + sn];
            sq += v * v;
        }
        const float* wp = ws + p * 4352;
        #pragma unroll
        for (int s = 0; s < 8; ++s){
            wmma::fragment<wmma::matrix_a, 16, 16, 8, wmma::precision::tf32, wmma::col_major> af;
            wmma::load_matrix_sync(af, xp + (8*s)*132 + 16*wid, 132);
            #pragma unroll
            for (int t = 0; t < af.num_elements; ++t) af.x[t] = wmma::__float_to_tf32(af.x[t]);
            #pragma unroll
            for (int j = 0; j < 4; ++j){
                wmma::fragment<wmma::matrix_b, 16, 16, 8, wmma::precision::tf32, wmma::col_major> bf;
                wmma::load_matrix_sync(bf, wp + (16*j)*68 + 8*s, 68);
                #pragma unroll
                for (int t = 0; t < bf.num_elements; ++t) bf.x[t] = wmma::__float_to_tf32(bf.x[t]);
                wmma::mma_sync(cfr[j], af, bf, cfr[j]);
            }
        }
        __syncthreads();
    }
#undef KA_STAGE

    // logits -> smem col-major [k][136n]; sumsq partials (both regions now dead)
    #pragma unroll
    for (int j = 0; j < 4; ++j)
        wmma::store_matrix_sync(logit_s + 16*wid + (16*j)*136, cfr[j], 136, wmma::mem_col_major);
    s_red[sh2*128 + sn] = sq;
    __syncthreads();

    if (tid < 128){
        const int n = tid, gn = n0 + n;
        const bool valid = gn < N_;
        float tot = s_red[n] + s_red[128 + n];
        float sinv = valid ? 1.f / fmaxf(sqrtf(tot), EPSF) : 0.f;

        float mx = -3.4e38f;
        #pragma unroll
        for (int k2 = 0; k2 < 64; ++k2)
            mx = fmaxf(mx, logit_s[k2*136 + n] * sinv);
        float se = 0.f;
        #pragma unroll
        for (int k2 = 0; k2 < 64; ++k2){
            float e = __expf(logit_s[k2*136 + n] * sinv - mx);
            logit_s[k2*136 + n] = e;
            se += e;
        }
        const float r  = 1.f / se;
        const float ri = r * sinv;   // 0 for padding pixels -> a' = 0

        float* ga = g_a + (size_t)(b*K_)*NPAD + gn;
        #pragma unroll
        for (int k2 = 0; k2 < 64; ++k2)
            ga[(size_t)k2*NPAD] = logit_s[k2*136 + n] * ri;

        #pragma unroll
        for (int k2 = 0; k2 < 64; ++k2){
            float v = valid ? logit_s[k2*136 + n] * r : 0.f;
            #pragma unroll
            for (int off = 16; off; off >>= 1)
                v += __shfl_xor_sync(0xffffffffu, v, off);
            if ((k2 & 31) == lid) s_wsum[wid*64 + k2] = v;
        }
    }
    __syncthreads();
    if (tid < 64)
        g_asum_part[(b*NT_ + tile)*K_ + tid] =
            s_wsum[tid] + s_wsum[64 + tid] + s_wsum[128 + tid] + s_wsum[192 + tid];
}

// ---------------------------------------------------------------------------
// KB: per (b, 128-d tile): vlad_gemm[128d x 64k] = x · a'^T via wmma TF32,
//     20 chunks of 64 n, cp.async double-buffered (x and a' both raw fp32;
//     a' padding region is exact zeros -> no masking). C stored straight to
//     gmem col-major (ldm = 512). Dynamic smem 102 KB -> 2 CTAs/SM.
// ---------------------------------------------------------------------------
__global__ __launch_bounds__(256) void kb_vlad(const float* __restrict__ x,
                                               float* __restrict__ out)
{
    extern __shared__ __align__(16) char DSM[];
    float* xs = reinterpret_cast<float*>(DSM);            // [2][128*68]
    float* as = reinterpret_cast<float*>(DSM + 69632);    // [2][64*68]

    const int tid = threadIdx.x, wid = tid >> 5;
    const int d0 = blockIdx.x * 128, b = blockIdx.y;
    const float* xb = x + (size_t)b * D_ * N_;
    const float* ab = g_a + (size_t)(b*K_)*NPAD;

    const u32 xs_sh = (u32)__cvta_generic_to_shared(xs);
    const u32 as_sh = (u32)__cvta_generic_to_shared(as);

#define KB_STAGE(p, ci) do{ const int nc_ = (ci)*64; \
    _Pragma("unroll") \
    for (int i_ = 0; i_ < 8; ++i_){ \
        int u_ = tid + 256*i_; int d_ = u_ >> 4, c4 = u_ & 15; \
        int gn_ = nc_ + 4*c4; bool v_ = gn_ < N_; \
        const float* s_ = v_ ? (xb + (size_t)(d0 + d_)*N_ + gn_) : xb; \
        u32 q_ = xs_sh + (u32)(p)*34816u + (u32)(d_*68 + 4*c4)*4u; \
        asm volatile("cp.async.cg.shared.global [%0], [%1], 16, %2;" \
                     :: "r"(q_), "l"(s_), "r"(v_ ? 16 : 0)); } \
    _Pragma("unroll") \
    for (int i_ = 0; i_ < 4; ++i_){ \
        int u_ = tid + 256*i_; int k_ = u_ >> 4, c4 = u_ & 15; \
        const float* s_ = ab + (size_t)k_*NPAD + nc_ + 4*c4; \
        u32 q_ = as_sh + (u32)(p)*17408u + (u32)(k_*68 + 4*c4)*4u; \
        asm volatile("cp.async.cg.shared.global [%0], [%1], 16;" :: "r"(q_), "l"(s_)); } \
    asm volatile("cp.async.commit_group;"); }while(0)

    wmma::fragment<wmma::accumulator, 16, 16, 8, float> cfr[4];
    #pragma unroll
    for (int j = 0; j < 4; ++j) wmma::fill_fragment(cfr[j], 0.f);

    KB_STAGE(0, 0);
    for (int ci = 0; ci < 20; ++ci){
        const int p = ci & 1;
        if (ci < 19){
            KB_STAGE(p ^ 1, ci + 1);
            asm volatile("cp.async.wait_group 1;");
        } else {
            asm volatile("cp.async.wait_group 0;");
        }
        __syncthreads();

        const float* xp = xs + p * 8704;
        const float* ap = as + p * 4352;
        #pragma unroll
        for (int s = 0; s < 8; ++s){
            wmma::fragment<wmma::matrix_a, 16, 16, 8, wmma::precision::tf32, wmma::row_major> af;
            wmma::load_matrix_sync(af, xp + (16*wid)*68 + 8*s, 68);
            #pragma unroll
            for (int t = 0; t < af.num_elements; ++t) af.x[t] = wmma::__float_to_tf32(af.x[t]);
            #pragma unroll
            for (int j = 0; j < 4; ++j){
                wmma::fragment<wmma::matrix_b, 16, 16, 8, wmma::precision::tf32, wmma::col_major> bf;
                wmma::load_matrix_sync(bf, ap + (16*j)*68 + 8*s, 68);
                #pragma unroll
                for (int t = 0; t < bf.num_elements; ++t) bf.x[t] = wmma::__float_to_tf32(bf.x[t]);
                wmma::mma_sync(cfr[j], af, bf, cfr[j]);
            }
        }
        __syncthreads();
    }
#undef KB_STAGE

    // C (d,k): out[(b*64 + k)*512 + d0 + d] -> col-major, ldm = D_
    #pragma unroll
    for (int j = 0; j < 4; ++j)
        wmma::store_matrix_sync(out + ((size_t)(b*K_ + 16*j))*D_ + d0 + 16*wid,
                                cfr[j], D_, wmma::mem_col_major);
}

// ---------------------------------------------------------------------------
// KC: asum from partials, centroid residual, intra-normalize; global L2
//     folded in (rows unit-norm -> global norm = sqrt(64) = 8 -> x0.125).
// ---------------------------------------------------------------------------
__global__ __launch_bounds__(128) void kc_norm(float* __restrict__ out,
                                               const float* __restrict__ cent)
{
    __shared__ float sh[128];
    const int k = blockIdx.x, b = blockIdx.y;
    const int tid = threadIdx.x;

    float s = (tid < NT_) ? g_asum_part[(b*NT_ + tid)*K_ + k] : 0.f;
    sh[tid] = s; __syncthreads();
    for (int o = 64; o; o >>= 1){ if (tid < o) sh[tid] += sh[tid + o]; __syncthreads(); }
    float asum = sh[0];
    __syncthreads();

    float*       row  = out  + ((size_t)(b*K_ + k))*D_;
    const float* crow = cent + (size_t)k*D_;
    float v[4]; float sq = 0.f;
    #pragma unroll
    for (int j = 0; j < 4; ++j){
        int d = tid + 128*j;
        v[j] = row[d] - asum * crow[d];
        sq += v[j]*v[j];
    }
    sh[tid] = sq; __syncthreads();
    for (int o = 64; o; o >>= 1){ if (tid < o) sh[tid] += sh[tid + o]; __syncthreads(); }
    float inv = 0.125f / fmaxf(sqrtf(sh[0]), EPSF);
    #pragma unroll
    for (int j = 0; j < 4; ++j) row[tid + 128*j] = v[j] * inv;
}

// ---------------------------------------------------------------------------
extern "C" void kernel_launch(void* const* d_in, const int* in_sizes, int n_in,
                              void* d_out, int out_size)
{
    const float* x = (const float*)d_in[0];   // (B, D, H, W)
    const float* w = (const float*)d_in[1];   // (K, D)
    const float* c = (const float*)d_in[2];   // (K, D)
    float* out = (float*)d_out;               // (B, K*D)

    cudaFuncSetAttribute(ka_logits, cudaFuncAttributeMaxDynamicSharedMemorySize, 102400);
    cudaFuncSetAttribute(kb_vlad,   cudaFuncAttributeMaxDynamicSharedMemorySize, 104448);

    ka_logits<<<dim3(NT_, B_), 256, 102400>>>(x, w);
    kb_vlad  <<<dim3(D_/128, B_), 256, 104448>>>(x, out);
    kc_norm  <<<dim3(K_, B_), 128>>>(out, c);
}